// round 1
// baseline (speedup 1.0000x reference)
#include <cuda_runtime.h>
#include <math.h>

#define EPSF 1e-6f
#define NUM_V 10
#define IMG_H 1500
#define IMG_W 2000
#define MAXN 65536

// ---------------- device scratch (no allocations allowed) ----------------
__device__ float g_start[MAXN * 3];
__device__ float g_dir[MAXN * 3];
__device__ float g_up[MAXN * 3];
__device__ float g_len[MAXN];
__device__ int   g_nh[MAXN];
__device__ double g_acc[3];          // sim_sum, normal_sum, normalization_sum
__device__ unsigned long long g_totx; // sum of num_h
__device__ float g_T[16];            // K2h @ E2 @ inv(E1)

// ---------------- setup: zero accumulators + compute T ----------------
__global__ void setup_kernel(const float* __restrict__ E1,
                             const float* __restrict__ E2,
                             const float* __restrict__ K2) {
    if (threadIdx.x != 0 || blockIdx.x != 0) return;
    g_acc[0] = 0.0; g_acc[1] = 0.0; g_acc[2] = 0.0;
    g_totx = 0ull;

    // Gauss-Jordan inverse of E1 (4x4, partial pivoting)
    float a[4][8];
    for (int i = 0; i < 4; i++)
        for (int j = 0; j < 4; j++) {
            a[i][j] = E1[i * 4 + j];
            a[i][j + 4] = (i == j) ? 1.0f : 0.0f;
        }
    for (int col = 0; col < 4; col++) {
        int p = col; float best = fabsf(a[col][col]);
        for (int r = col + 1; r < 4; r++) {
            float v = fabsf(a[r][col]);
            if (v > best) { best = v; p = r; }
        }
        if (p != col) {
            for (int j = 0; j < 8; j++) { float t = a[col][j]; a[col][j] = a[p][j]; a[p][j] = t; }
        }
        float d = a[col][col];
        for (int j = 0; j < 8; j++) a[col][j] /= d;
        for (int r = 0; r < 4; r++) {
            if (r == col) continue;
            float f = a[r][col];
            for (int j = 0; j < 8; j++) a[r][j] -= f * a[col][j];
        }
    }
    float inv[16];
    for (int i = 0; i < 4; i++)
        for (int j = 0; j < 4; j++) inv[i * 4 + j] = a[i][j + 4];

    // M = E2 @ inv(E1)
    float M[16];
    for (int i = 0; i < 4; i++)
        for (int j = 0; j < 4; j++) {
            float s = 0.0f;
            for (int k = 0; k < 4; k++) s += E2[i * 4 + k] * inv[k * 4 + j];
            M[i * 4 + j] = s;
        }
    // T = K2h @ M, K2h = eye(4) with K2 in [:3,:3]
    for (int j = 0; j < 4; j++) {
        for (int i = 0; i < 3; i++) {
            float s = 0.0f;
            for (int k = 0; k < 3; k++) s += K2[i * 3 + k] * M[k * 4 + j];
            g_T[i * 4 + j] = s;
        }
        g_T[12 + j] = M[12 + j];
    }
}

// ---------------- per-edge precompute + edge-level losses ----------------
__device__ __forceinline__ void cross3(const float* u, const float* v, float* w) {
    w[0] = u[1] * v[2] - u[2] * v[1];
    w[1] = u[2] * v[0] - u[0] * v[2];
    w[2] = u[0] * v[1] - u[1] * v[0];
}
__device__ __forceinline__ float norm3(const float* u) {
    return sqrtf(u[0] * u[0] + u[1] * u[1] + u[2] * u[2]);
}

__global__ void edge_kernel(const float* __restrict__ ep, int N) {
    int i = blockIdx.x * blockDim.x + threadIdx.x;
    float nloss = 0.0f, zloss = 0.0f;
    int nh_local = 0;
    if (i < N && i < MAXN) {
        const float* e = ep + (size_t)i * 12;
        float p0[3] = { e[0], e[1], e[2] };
        float p1[3] = { e[3], e[4], e[5] };
        float p2[3] = { e[6], e[7], e[8] };
        float p3[3] = { e[9], e[10], e[11] };

        float cd[3] = { p1[0] - p0[0], p1[1] - p0[1], p1[2] - p0[2] };
        float nd[3] = { p3[0] - p1[0], p3[1] - p1[1], p3[2] - p1[2] };
        float pd[3] = { p0[0] - p2[0], p0[1] - p2[1], p0[2] - p2[2] };

        // cur_len = ||cd + EPS|| (elementwise EPS, as reference)
        float ce[3] = { cd[0] + EPSF, cd[1] + EPSF, cd[2] + EPSF };
        float cl = norm3(ce);
        float dir[3] = { cd[0] / cl, cd[1] / cl, cd[2] / cl };

        float cn[3]; cross3(dir, nd, cn);
        float cnn = norm3(cn) + EPSF;
        cn[0] /= cnn; cn[1] /= cnn; cn[2] /= cnn;
        if (cn[2] > 0.0f) { cn[0] = -cn[0]; cn[1] = -cn[1]; cn[2] = -cn[2]; }

        float up[3]; cross3(cn, dir, up);
        float upn = norm3(up) + EPSF;
        up[0] /= upn; up[1] /= upn; up[2] /= upn;

        float pn[3]; cross3(pd, dir, pn);
        float pnn = norm3(pn) + EPSF;
        pn[0] /= pnn; pn[1] /= pnn; pn[2] /= pnn;

        // num_h = clip(floor(cl/0.05), 2, 1000)
        int nh = (int)floorf(cl / 0.05f);
        nh = max(2, min(1000, nh));

        g_start[i * 3 + 0] = p0[0]; g_start[i * 3 + 1] = p0[1]; g_start[i * 3 + 2] = p0[2];
        g_dir[i * 3 + 0] = dir[0];  g_dir[i * 3 + 1] = dir[1];  g_dir[i * 3 + 2] = dir[2];
        g_up[i * 3 + 0] = up[0];    g_up[i * 3 + 1] = up[1];    g_up[i * 3 + 2] = up[2];
        g_len[i] = cl;
        g_nh[i] = nh;
        nh_local = nh;

        // normal loss term: 1 - dot(cur_normal, prev_normal)
        nloss = 1.0f - (cn[0] * pn[0] + cn[1] * pn[1] + cn[2] * pn[2]);

        // normalization loss term
        float obs[3]; cross3(p0, p1, obs);
        float obn = norm3(obs) + EPSF;
        obs[0] /= obn; obs[1] /= obn; obs[2] /= obn;
        float snp = fabsf(up[0] * obs[0] + up[1] * obs[1] + up[2] * obs[2]);
        snp = fminf(snp, 0.5f);
        zloss = 1.0f - snp * 2.0f;
    }
    // warp reduce + atomics
    for (int o = 16; o > 0; o >>= 1) {
        nloss += __shfl_down_sync(0xffffffffu, nloss, o);
        zloss += __shfl_down_sync(0xffffffffu, zloss, o);
        nh_local += __shfl_down_sync(0xffffffffu, nh_local, o);
    }
    if ((threadIdx.x & 31) == 0) {
        atomicAdd(&g_acc[1], (double)nloss);
        atomicAdd(&g_acc[2], (double)zloss);
        atomicAdd(&g_totx, (unsigned long long)nh_local);
    }
}

// ---------------- bilinear sample (channel-first image) ----------------
__device__ __forceinline__ void fetch3(const float* __restrict__ im,
                                       float u, float v, float out[3]) {
    float x = u * (float)(IMG_W - 1);
    float y = v * (float)(IMG_H - 1);
    float fx = floorf(x), fy = floorf(y);
    int x0 = (int)fx, y0 = (int)fy;
    int x1 = min(x0 + 1, IMG_W - 1);
    int y1 = min(y0 + 1, IMG_H - 1);
    float wx = x - fx, wy = y - fy;
    float w00 = (1.0f - wx) * (1.0f - wy);
    float w10 = wx * (1.0f - wy);
    float w01 = (1.0f - wx) * wy;
    float w11 = wx * wy;
    int b00 = y0 * IMG_W + x0;
    int b10 = y0 * IMG_W + x1;
    int b01 = y1 * IMG_W + x0;
    int b11 = y1 * IMG_W + x1;
#pragma unroll
    for (int c = 0; c < 3; c++) {
        const float* p = im + (size_t)c * (IMG_H * IMG_W);
        float v00 = __ldg(p + b00);
        float v10 = __ldg(p + b10);
        float v01 = __ldg(p + b01);
        float v11 = __ldg(p + b11);
        out[c] = v00 * w00 + v10 * w10 + v01 * w01 + v11 * w11;
    }
}

// ---------------- sample kernel: one block per edge ----------------
__global__ void __launch_bounds__(256, 8)
sample_kernel(const float* __restrict__ rgb1,
              const float* __restrict__ rgb2,
              const float* __restrict__ K1) {
    int e = blockIdx.x;
    int nh = g_nh[e];
    float sx = g_start[e * 3 + 0], sy = g_start[e * 3 + 1], sz = g_start[e * 3 + 2];
    float dx = g_dir[e * 3 + 0],  dyv = g_dir[e * 3 + 1],  dz = g_dir[e * 3 + 2];
    float ux = g_up[e * 3 + 0],   uy = g_up[e * 3 + 1],    uz = g_up[e * 3 + 2];
    float clen = g_len[e];
    float denomf = (float)(nh - 1);

    float k0 = K1[0], k1 = K1[1], k2 = K1[2];
    float k3 = K1[3], k4 = K1[4], k5 = K1[5];
    float k6 = K1[6], k7 = K1[7], k8 = K1[8];
    float t0 = g_T[0], t1 = g_T[1], t2 = g_T[2], t3 = g_T[3];
    float t4 = g_T[4], t5 = g_T[5], t6 = g_T[6], t7 = g_T[7];
    float t8 = g_T[8], t9 = g_T[9], t10 = g_T[10], t11 = g_T[11];

    int total = nh * NUM_V;
    float local = 0.0f;
    for (int s = threadIdx.x; s < total; s += blockDim.x) {
        int hx = s / NUM_V;
        int dy = s - hx * NUM_V;
        float cx = ((float)hx / denomf) * clen;
        float cy = ((float)dy / (float)(NUM_V - 1)) * 0.5f;
        float px = dx * cx + ux * cy + sx;
        float py = dyv * cx + uy * cy + sy;
        float pz = dz * cx + uz * cy + sz;

        // camera 1
        float u1 = k0 * px + k1 * py + k2 * pz;
        float v1 = k3 * px + k4 * py + k5 * pz;
        float w1 = k6 * px + k7 * py + k8 * pz;
        u1 = fminf(fmaxf(u1 / w1, 0.0f), 0.999999f);
        v1 = fminf(fmaxf(v1 / w1, 0.0f), 0.999999f);

        // camera 2 via T (homogeneous)
        float u2 = t0 * px + t1 * py + t2 * pz + t3;
        float v2 = t4 * px + t5 * py + t6 * pz + t7;
        float w2 = t8 * px + t9 * py + t10 * pz + t11;
        u2 = fminf(fmaxf(u2 / w2, 0.0f), 0.999999f);
        v2 = fminf(fmaxf(v2 / w2, 0.0f), 0.999999f);

        float s1[3], s2[3];
        fetch3(rgb1, u1, v1, s1);
        fetch3(rgb2, u2, v2, s2);
        float d0 = s1[0] - s2[0];
        float d1 = s1[1] - s2[1];
        float d2 = s1[2] - s2[2];
        local += d0 * d0 + d1 * d1 + d2 * d2;
    }

    // block reduce
    for (int o = 16; o > 0; o >>= 1)
        local += __shfl_down_sync(0xffffffffu, local, o);
    __shared__ float warpsum[8];
    int wid = threadIdx.x >> 5;
    if ((threadIdx.x & 31) == 0) warpsum[wid] = local;
    __syncthreads();
    if (threadIdx.x == 0) {
        float bs = 0.0f;
        int nw = (blockDim.x + 31) >> 5;
        for (int w = 0; w < nw; w++) bs += warpsum[w];
        atomicAdd(&g_acc[0], (double)bs);
    }
}

// ---------------- finalize ----------------
__global__ void finalize_kernel(float* __restrict__ out, int N) {
    if (threadIdx.x != 0 || blockIdx.x != 0) return;
    double totalSamples = (double)g_totx * (double)NUM_V * 3.0;
    out[0] = (float)(g_acc[0] / totalSamples);
    out[1] = (float)(g_acc[1] / (double)N / 2.0);
    out[2] = (float)(g_acc[2] / (double)N);
}

// ---------------- launch ----------------
extern "C" void kernel_launch(void* const* d_in, const int* in_sizes, int n_in,
                              void* d_out, int out_size) {
    const float* edge_points = (const float*)d_in[0];
    const float* intrinsic1  = (const float*)d_in[1];
    const float* intrinsic2  = (const float*)d_in[2];
    const float* extrinsic1  = (const float*)d_in[3];
    const float* extrinsic2  = (const float*)d_in[4];
    const float* rgb1        = (const float*)d_in[5];
    const float* rgb2        = (const float*)d_in[6];
    float* out = (float*)d_out;

    int N = in_sizes[0] / 12;

    setup_kernel<<<1, 1>>>(extrinsic1, extrinsic2, intrinsic2);
    edge_kernel<<<(N + 255) / 256, 256>>>(edge_points, N);
    sample_kernel<<<N, 256>>>(rgb1, rgb2, intrinsic1);
    finalize_kernel<<<1, 1>>>(out, N);
}